// round 11
// baseline (speedup 1.0000x reference)
#include <cuda_runtime.h>

// depthconv1d: B=8, L=16384, C=512, K=31, SAME padding, fp32 NWC.
// out[b,w,c] = sum_k x[b, w+k-15, c] * ker[k*C + c] + bias[c]
//
// R11 = R1 (best measured DRAM BW: 64.8%, 5.13 TB/s) + cache-policy tweaks:
//   - st.global.cs streaming stores: out has zero reuse; evict-first keeps
//     the x halo lines resident in L2 (halo reuse is what holds DRAM reads
//     at the 1.0x compulsory level).
//   - __ldg read-only path for x and weights.
// Core structure untouched (resident weights, T=16, f32x2 FMA, 2 CTAs/SM):
// across 8 measured variants dur ~= 512MB / achieved_BW, so the only lever
// left is achieved BW, and R1's issue stream (alu 4.6%) was the cleanest.

#define B_ 8
#define L_ 16384
#define C_ 512
#define K_ 31
#define HALF_ 15
#define T_ 16   // output positions per thread

using u64 = unsigned long long;

__device__ __forceinline__ u64 fma2(u64 a, u64 b, u64 c) {
    u64 d;
    asm("fma.rn.f32x2 %0, %1, %2, %3;" : "=l"(d) : "l"(a), "l"(b), "l"(c));
    return d;
}
__device__ __forceinline__ u64 add2(u64 a, u64 b) {
    u64 d;
    asm("add.rn.f32x2 %0, %1, %2;" : "=l"(d) : "l"(a), "l"(b));
    return d;
}
__device__ __forceinline__ u64 ldg_nc64(const void* p) {
    u64 v;
    asm("ld.global.nc.b64 %0, [%1];" : "=l"(v) : "l"(p));
    return v;
}
__device__ __forceinline__ void stcs64(void* p, u64 v) {
    asm volatile("st.global.cs.b64 [%0], %1;" :: "l"(p), "l"(v) : "memory");
}

template <bool EDGE>
__device__ __forceinline__ void conv_body(
    const float* __restrict__ x, const float* __restrict__ w,
    const float* __restrict__ bias, float* __restrict__ out,
    int b, int w0, int cb)
{
    // Per-thread packed weights: ker[k*C + cb .. cb+1] as one 64-bit value.
    u64 wk[K_];
#pragma unroll
    for (int k = 0; k < K_; k++)
        wk[k] = ldg_nc64(w + k * C_ + cb);

    u64 acc[T_];
#pragma unroll
    for (int t = 0; t < T_; t++) acc[t] = 0ull;

    // Base pointer at (b, w0 - HALF, cb). Row stride = C_ floats = 2048 B.
    const char* xb = reinterpret_cast<const char*>(x)
                   + ((long long)((long long)b * L_ + w0 - HALF_) * C_ + cb) * 4ll;

    // Stream T_+K_-1 = 46 input rows; each feeds up to 31 outputs.
#pragma unroll
    for (int p = 0; p < T_ + K_ - 1; p++) {
        u64 xv;
        if (EDGE) {
            int wg = w0 - HALF_ + p;
            xv = (wg >= 0 && wg < L_)
                 ? ldg_nc64(xb + (long long)p * (C_ * 4))
                 : 0ull;
        } else {
            xv = ldg_nc64(xb + (long long)p * (C_ * 4));
        }
#pragma unroll
        for (int t = 0; t < T_; t++) {
            int k = p - t;
            if (k >= 0 && k < K_)
                acc[t] = fma2(xv, wk[k], acc[t]);
        }
    }

    u64 bv = ldg_nc64(bias + cb);
    char* ob = reinterpret_cast<char*>(out)
             + ((long long)((long long)b * L_ + w0) * C_ + cb) * 4ll;
#pragma unroll
    for (int t = 0; t < T_; t++)
        stcs64(ob + (long long)t * (C_ * 4), add2(acc[t], bv));
}

__global__ __launch_bounds__(256, 2)
void depthconv1d_kernel(const float* __restrict__ x,
                        const float* __restrict__ w,
                        const float* __restrict__ bias,
                        float* __restrict__ out)
{
    int cb   = threadIdx.x * 2;        // channel pair base (0..510)
    int tile = blockIdx.x;             // L tile index
    int b    = blockIdx.y;             // batch
    int w0   = tile * T_;

    if (tile == 0 || tile == (L_ / T_ - 1))
        conv_body<true>(x, w, bias, out, b, w0, cb);
    else
        conv_body<false>(x, w, bias, out, b, w0, cb);
}

extern "C" void kernel_launch(void* const* d_in, const int* in_sizes, int n_in,
                              void* d_out, int out_size)
{
    const float* x    = (const float*)d_in[0];  // [8, 16384, 512]
    const float* ker  = (const float*)d_in[1];  // [31, 512, 1]
    const float* bias = (const float*)d_in[2];  // [512]
    float* out = (float*)d_out;                 // [8, 16384, 512]

    dim3 grid(L_ / T_, B_);   // (1024, 8)
    dim3 block(256);          // 2 channels per thread -> 512 channels
    depthconv1d_kernel<<<grid, block>>>(x, ker, bias, out);
}

// round 12
// speedup vs baseline: 1.2247x; 1.2247x over previous
#include <cuda_runtime.h>
#include <cstdint>

// depthconv1d: B=8, L=16384, C=512, K=31, SAME padding, fp32 NWC.
// out[b,w,c] = sum_k x[b, w+k-15, c] * ker[k*C + c] + bias[c]
//
// R12: barrier-free warp-paced pipelines. Each of 8 warps owns a private
// double-buffered smem pair (7.9KB each) and walks NITER=8 tiles of
// 32 rows x 32 channels, waiting ONLY on its own cp.async groups
// (wait_group + __syncwarp; zero __syncthreads after entry). 8 independent
// continuously-loading streams per SM: fixes R6 (CTA lockstep) and R4/R8
// (one-shot dead time). Weights via plain LDG (L1). Plain C++ derefs for
// all loads/stores (R11 lesson: asm wrappers kill ptxas batching).

#define B_ 8
#define L_ 16384
#define C_ 512
#define K_ 31
#define HALF_ 15
#define T_ 16                    // outputs per thread
#define WB_ 32                   // rows per tile per warp
#define CBW_ 32                  // channels per warp
#define NWARP_ 8
#define CB_ (CBW_ * NWARP_)      // 256 channels per CTA
#define NITER_ 8                 // tiles walked per warp
#define NR_ (WB_ + K_ - 1)       // 62 staged rows per buffer
#define ROWB_ (CBW_ * 4)         // 128 B per staged row
#define BUFB_ (NR_ * ROWB_)      // 7936 B per buffer
#define SMEM_TOTAL_ (NWARP_ * 2 * BUFB_)   // 126976 B
#define XW_ 18                   // register x-ring slots
#define NP_ (T_ + K_ - 1)        // 46 rows read per thread per tile

using u64 = unsigned long long;

__device__ __forceinline__ u64 fma2(u64 a, u64 b, u64 c) {
    u64 d;
    asm("fma.rn.f32x2 %0, %1, %2, %3;" : "=l"(d) : "l"(a), "l"(b), "l"(c));
    return d;
}
__device__ __forceinline__ u64 add2(u64 a, u64 b) {
    u64 d;
    asm("add.rn.f32x2 %0, %1, %2;" : "=l"(d) : "l"(a), "l"(b));
    return d;
}
__device__ __forceinline__ void cp_async16(uint32_t sa, const void* g) {
    asm volatile("cp.async.cg.shared.global [%0], [%1], 16;"
                 :: "r"(sa), "l"(g) : "memory");
}
#define CP_COMMIT() asm volatile("cp.async.commit_group;" ::: "memory")
#define CP_WAIT1()  asm volatile("cp.async.wait_group 1;"  ::: "memory")

// Stage NR_=62 rows x 128B = 496 16B chunks across the warp's 32 lanes.
template <bool EDGE>
__device__ __forceinline__ void load_buf(char* dst, uint32_t dsta,
                                         const char* gx, int row0, int lane)
{
#pragma unroll
    for (int rnd = 0; rnd < 16; rnd++) {
        int chunk = rnd * 32 + lane;
        if (chunk < NR_ * 8) {
            int r = chunk >> 3, c = chunk & 7;
            int wg = row0 + r;
            if (!EDGE || ((unsigned)wg < (unsigned)L_)) {
                cp_async16(dsta + r * ROWB_ + c * 16,
                           gx + (long long)wg * (C_ * 4) + c * 16);
            } else {
                *reinterpret_cast<uint4*>(dst + r * ROWB_ + c * 16)
                    = make_uint4(0u, 0u, 0u, 0u);
            }
        }
    }
}

template <bool EDGE>
__device__ __forceinline__ void run_body(
    const float* __restrict__ x, const float* __restrict__ w,
    const float* __restrict__ bias, float* __restrict__ out, char* smem)
{
    const int tid  = threadIdx.x;
    const int wid  = tid >> 5;
    const int lane = tid & 31;
    const int cb0  = blockIdx.y * CB_ + wid * CBW_;   // warp's 32 channels
    const int b    = blockIdx.z;
    const int W0   = blockIdx.x * (WB_ * NITER_);

    char* buf0 = smem + wid * 2 * BUFB_;
    char* buf1 = buf0 + BUFB_;
    uint32_t ba0 = (uint32_t)__cvta_generic_to_shared(buf0);
    uint32_t ba1 = ba0 + BUFB_;

    const char* gx = reinterpret_cast<const char*>(x)
                   + ((long long)b * L_ * C_ + cb0) * 4ll;

    // ---- Prime the warp's pipeline: tiles 0 and 1 ----
    load_buf<EDGE>(buf0, ba0, gx, W0 - HALF_, lane);
    CP_COMMIT();                                     // group 0 = tile 0
    load_buf<EDGE>(buf1, ba1, gx, W0 - HALF_ + WB_, lane);
    CP_COMMIT();                                     // group 1 = tile 1

    const int pair = lane & 15;                      // channels cb0 + 2*pair
    const int grp  = lane >> 4;                      // w-subgroup 0..1
    const float* wgp = w + cb0 + pair * 2;           // weight LDG base (L1)
    const u64 bv = *reinterpret_cast<const u64*>(bias + cb0 + pair * 2);
    char* ob0 = reinterpret_cast<char*>(out)
              + ((long long)((long long)b * L_ + W0 + grp * T_) * C_
                 + cb0 + pair * 2) * 4ll;

#pragma unroll 1
    for (int i = 0; i < NITER_; i++) {
        // Committed groups: i+2. wait_group 1 -> groups 0..i landed (this
        // lane); __syncwarp -> all lanes past their waits, so the whole
        // buffer for tile i is visible.
        CP_WAIT1();
        __syncwarp();

        const char* xsp = ((i & 1) ? buf1 : buf0)
                        + (grp * T_) * ROWB_ + pair * 8;

        u64 xv[XW_];
#pragma unroll
        for (int p = 0; p < XW_; p++)
            xv[p] = *reinterpret_cast<const u64*>(xsp + p * ROWB_);

        u64 acc[T_];
#pragma unroll
        for (int t = 0; t < T_; t++) acc[t] = 0ull;

        u64 wcur = *reinterpret_cast<const u64*>(wgp);
#pragma unroll
        for (int k = 0; k < K_; k++) {
            u64 wnext = 0ull;
            if (k + 1 < K_)
                wnext = *reinterpret_cast<const u64*>(wgp + (k + 1) * C_);
#pragma unroll
            for (int t = 0; t < T_; t++)
                acc[t] = fma2(xv[(k + t) % XW_], wcur, acc[t]);
            if (k + XW_ < NP_)
                xv[(k + XW_) % XW_] =
                    *reinterpret_cast<const u64*>(xsp + (k + XW_) * ROWB_);
            wcur = wnext;
        }

        char* ob = ob0 + (long long)i * WB_ * (C_ * 4);
#pragma unroll
        for (int t = 0; t < T_; t++)
            *reinterpret_cast<u64*>(ob + (long long)t * (C_ * 4))
                = add2(acc[t], bv);

        __syncwarp();   // all lanes done reading buf(i&1) before refill
        if (i + 2 < NITER_) {
            if (i & 1) load_buf<EDGE>(buf1, ba1, gx,
                                      W0 - HALF_ + (i + 2) * WB_, lane);
            else       load_buf<EDGE>(buf0, ba0, gx,
                                      W0 - HALF_ + (i + 2) * WB_, lane);
        }
        CP_COMMIT();    // unconditional: keeps the group ledger in step
    }
}

__global__ __launch_bounds__(256, 1)
void depthconv1d_kernel(const float* __restrict__ x,
                        const float* __restrict__ w,
                        const float* __restrict__ bias,
                        float* __restrict__ out)
{
    extern __shared__ char smem[];
    if (blockIdx.x == 0 || blockIdx.x == gridDim.x - 1)
        run_body<true>(x, w, bias, out, smem);
    else
        run_body<false>(x, w, bias, out, smem);
}

extern "C" void kernel_launch(void* const* d_in, const int* in_sizes, int n_in,
                              void* d_out, int out_size)
{
    const float* x    = (const float*)d_in[0];  // [8, 16384, 512]
    const float* ker  = (const float*)d_in[1];  // [31, 512, 1]
    const float* bias = (const float*)d_in[2];  // [512]
    float* out = (float*)d_out;                 // [8, 16384, 512]

    cudaFuncSetAttribute(depthconv1d_kernel,
                         cudaFuncAttributeMaxDynamicSharedMemorySize,
                         SMEM_TOTAL_);

    dim3 grid(L_ / (WB_ * NITER_), C_ / CB_, B_);   // (64, 2, 8) = 1024
    dim3 block(256);
    depthconv1d_kernel<<<grid, block, SMEM_TOTAL_>>>(x, ker, bias, out);
}

// round 13
// speedup vs baseline: 1.2784x; 1.0439x over previous
#include <cuda_runtime.h>
#include <cstdint>

// depthconv1d: B=8, L=16384, C=512, K=31, SAME padding, fp32 NWC.
// out[b,w,c] = sum_k x[b, w+k-15, c] * ker[k*C + c] + bias[c]
//
// R13: TRIPLE-buffered cp.async pipeline. Key insight from R6's failure:
// with 2 buffers the load of tile i+2 can only be issued AFTER compute of
// tile i (its target buffer is busy until then) -> DRAM idle ~2/3 of each
// iteration. With 3 buffers the load for tile i+2 issues at the TOP of
// iteration i (its buffer holds consumed tile i-1) -> a full 31KB tile load
// is in flight during every compute phase. Per-SM demand (~76GB/s) >> HBM
// fair share, so DRAM should now pin near its true max.
// Core = R4 champion (CB=128, WB=32, T=16, k-outer ring, weights in smem).

#define B_ 8
#define L_ 16384
#define C_ 512
#define K_ 31
#define HALF_ 15
#define T_ 16                    // outputs per thread
#define CB_ 128                  // channels per block
#define WB_ 32                   // output rows per tile (2 grps x T)
#define NITER_ 8                 // tiles per CTA
#define NBUF_ 3
#define NR_ (WB_ + K_ - 1)       // 62 staged rows per buffer
#define ROWB_ (CB_ * 4)          // 512 B per staged row
#define BUFB_ (NR_ * ROWB_)      // 31744 B per buffer
#define WSB_ (K_ * ROWB_)        // 15872 B weights
#define SMEM_TOTAL_ (NBUF_ * BUFB_ + WSB_)   // 111104 B -> 2 CTAs/SM
#define XW_ 18                   // register x-ring slots
#define NP_ (T_ + K_ - 1)        // 46 rows read per thread per tile

using u64 = unsigned long long;

__device__ __forceinline__ u64 fma2(u64 a, u64 b, u64 c) {
    u64 d;
    asm("fma.rn.f32x2 %0, %1, %2, %3;" : "=l"(d) : "l"(a), "l"(b), "l"(c));
    return d;
}
__device__ __forceinline__ u64 add2(u64 a, u64 b) {
    u64 d;
    asm("add.rn.f32x2 %0, %1, %2;" : "=l"(d) : "l"(a), "l"(b));
    return d;
}
__device__ __forceinline__ void cp_async16(uint32_t sa, const void* g) {
    asm volatile("cp.async.cg.shared.global [%0], [%1], 16;"
                 :: "r"(sa), "l"(g) : "memory");
}
#define CP_COMMIT() asm volatile("cp.async.commit_group;" ::: "memory")
#define CP_WAIT2()  asm volatile("cp.async.wait_group 2;"  ::: "memory")

// Stage NR_=62 rows x 512B = 1984 16B chunks over 128 threads (16 rounds).
template <bool EDGE>
__device__ __forceinline__ void load_buf(char* dst, uint32_t dsta,
                                         const char* gx, int row0, int tid)
{
#pragma unroll
    for (int j = 0; j < 16; j++) {
        int chunk = j * 128 + tid;
        if (chunk < NR_ * 32) {
            int r = chunk >> 5, lane = chunk & 31;
            int wg = row0 + r;
            if (!EDGE || ((unsigned)wg < (unsigned)L_)) {
                cp_async16(dsta + r * ROWB_ + lane * 16,
                           gx + (long long)wg * (C_ * 4) + lane * 16);
            } else {
                *reinterpret_cast<uint4*>(dst + r * ROWB_ + lane * 16)
                    = make_uint4(0u, 0u, 0u, 0u);
            }
        }
    }
}

template <bool EDGE>
__device__ __forceinline__ void run_body(
    const float* __restrict__ x, const float* __restrict__ w,
    const float* __restrict__ bias, float* __restrict__ out, char* smem)
{
    char* ws = smem + NBUF_ * BUFB_;
    const int tid = threadIdx.x;
    const int cb0 = blockIdx.y * CB_;
    const int b   = blockIdx.z;
    const int W0  = blockIdx.x * (WB_ * NITER_);

    const char* gx = reinterpret_cast<const char*>(x)
                   + ((long long)b * L_ * C_ + cb0) * 4ll;
    uint32_t sa0 = (uint32_t)__cvta_generic_to_shared(smem);
    uint32_t wsa = sa0 + NBUF_ * BUFB_;

    // ---- Prologue ----
    // Weights: 31 rows x 512B = 992 chunks over 128 threads (8 rounds).
#pragma unroll
    for (int j = 0; j < 8; j++) {
        int chunk = j * 128 + tid;
        if (chunk < K_ * 32) {
            int k = chunk >> 5, lane = chunk & 31;
            cp_async16(wsa + k * ROWB_ + lane * 16,
                       reinterpret_cast<const char*>(w)
                       + ((long long)k * C_ + cb0) * 4ll + lane * 16);
        }
    }
    load_buf<EDGE>(smem, sa0, gx, W0 - HALF_, tid);
    CP_COMMIT();                                   // G0 = weights + tile0
    load_buf<EDGE>(smem + BUFB_, sa0 + BUFB_, gx, W0 - HALF_ + WB_, tid);
    CP_COMMIT();                                   // G1 = tile1

    const int pair = tid & 63;                     // channel pair 0..63
    const int grp  = tid >> 6;                     // w-subgroup 0..1
    const u64 bv = *reinterpret_cast<const u64*>(bias + cb0 + pair * 2);
    const char* wsp = ws + pair * 8;
    char* ob0 = reinterpret_cast<char*>(out)
              + ((long long)((long long)b * L_ + W0 + grp * T_) * C_
                 + cb0 + pair * 2) * 4ll;

#pragma unroll 1
    for (int i = 0; i < NITER_; i++) {
        // Issue load for tile i+2 into buffer (i+2)%3 FIRST: that buffer
        // holds tile i-1, fully consumed (trailing __syncthreads of iter
        // i-1). DRAM now has a full tile in flight during this compute.
        {
            int bi = (i + 2) % NBUF_;
            if (i + 2 < NITER_)
                load_buf<EDGE>(smem + bi * BUFB_, sa0 + bi * BUFB_,
                               gx, W0 - HALF_ + (i + 2) * WB_, tid);
        }
        CP_COMMIT();   // unconditional: committed groups now = i+3

        // wait_group 2 -> groups 0..i complete -> buffer i%3 landed.
        CP_WAIT2();
        __syncthreads();

        const char* xsp = smem + (i % NBUF_) * BUFB_
                        + (grp * T_) * ROWB_ + pair * 8;

        // k-outer compute with register x-ring sourced from SMEM.
        u64 xv[XW_];
#pragma unroll
        for (int p = 0; p < XW_; p++)
            xv[p] = *reinterpret_cast<const u64*>(xsp + p * ROWB_);

        u64 acc[T_];
#pragma unroll
        for (int t = 0; t < T_; t++) acc[t] = 0ull;

        u64 wcur = *reinterpret_cast<const u64*>(wsp);
#pragma unroll
        for (int k = 0; k < K_; k++) {
            u64 wnext = 0ull;
            if (k + 1 < K_)
                wnext = *reinterpret_cast<const u64*>(wsp + (k + 1) * ROWB_);
#pragma unroll
            for (int t = 0; t < T_; t++)
                acc[t] = fma2(xv[(k + t) % XW_], wcur, acc[t]);
            if (k + XW_ < NP_)
                xv[(k + XW_) % XW_] =
                    *reinterpret_cast<const u64*>(xsp + (k + XW_) * ROWB_);
            wcur = wnext;
        }

        char* ob = ob0 + (long long)i * WB_ * (C_ * 4);
#pragma unroll
        for (int t = 0; t < T_; t++)
            *reinterpret_cast<u64*>(ob + (long long)t * (C_ * 4))
                = add2(acc[t], bv);

        __syncthreads();   // all warps done with buffer i%3 before the
                           // NEXT iteration's load-issue overwrites it+3
    }
}

__global__ __launch_bounds__(128, 2)
void depthconv1d_kernel(const float* __restrict__ x,
                        const float* __restrict__ w,
                        const float* __restrict__ bias,
                        float* __restrict__ out)
{
    extern __shared__ char smem[];
    if (blockIdx.x == 0 || blockIdx.x == gridDim.x - 1)
        run_body<true>(x, w, bias, out, smem);
    else
        run_body<false>(x, w, bias, out, smem);
}

extern "C" void kernel_launch(void* const* d_in, const int* in_sizes, int n_in,
                              void* d_out, int out_size)
{
    const float* x    = (const float*)d_in[0];  // [8, 16384, 512]
    const float* ker  = (const float*)d_in[1];  // [31, 512, 1]
    const float* bias = (const float*)d_in[2];  // [512]
    float* out = (float*)d_out;                 // [8, 16384, 512]

    cudaFuncSetAttribute(depthconv1d_kernel,
                         cudaFuncAttributeMaxDynamicSharedMemorySize,
                         SMEM_TOTAL_);

    dim3 grid(L_ / (WB_ * NITER_), C_ / CB_, B_);   // (64, 4, 8) = 2048
    dim3 block(128);
    depthconv1d_kernel<<<grid, block, SMEM_TOTAL_>>>(x, ker, bias, out);
}